// round 7
// baseline (speedup 1.0000x reference)
#include <cuda_runtime.h>
#include <cuda_bf16.h>

// Shapes (fixed): B=32, D=64, N=254, L=16, H=128, P=96
#define NB 32
#define ND 64
#define NN 254
#define NL 16
#define NH 128
#define NP 96
#define PAIRS (NB*ND)          // 2048
#define XPP (NN*NL)            // 4064 floats per (b,d) pair
#define OUT_T_ELEMS (NB*NP*ND) // 196608
#define NPRE 38                // producer blocks in K1

// ---- shared precomputed tensors (tiny) ----
__device__ __align__(16) float g_constvec[NH];
__device__ __align__(16) float g_M[NN*NL];   // M[n,l] = pos[n,:] . W_enc[l,:]
__device__ __align__(16) float g_D2[NN];     // pos[n,:] . constvec
__device__ __align__(16) float g_G[NL*NL];   // G[l',l] = W_enc[l',:] . W_enc[l,:]
__device__ __align__(16) float g_u[NL];      // W_enc[l,:] . constvec
__device__ __align__(16) float g_wb[NL];     // W_enc[l,:] . b_enc
__device__ float g_s0;                        // b_enc . constvec
__device__ __align__(16) float g_xsum[PAIRS*NL]; // per-pair xsum
__device__ int g_flag1;                       // constvec ready (monotone across replays)

__device__ __forceinline__ int ld_acq(const int* p) {
    int v;
    asm volatile("ld.acquire.gpu.global.b32 %0, [%1];" : "=r"(v) : "l"(p));
    return v;
}

// vectorized length-128 dot with 4 accumulators
__device__ __forceinline__ float dot128(const float4* __restrict__ a,
                                        const float4* __restrict__ b) {
    float s0=0.f, s1=0.f, s2=0.f, s3=0.f;
    #pragma unroll
    for (int i = 0; i < 32; i += 4) {
        float4 a0=a[i],   b0=b[i];
        float4 a1=a[i+1], b1=b[i+1];
        float4 a2=a[i+2], b2=b[i+2];
        float4 a3=a[i+3], b3=b[i+3];
        s0 += a0.x*b0.x + a0.y*b0.y + a0.z*b0.z + a0.w*b0.w;
        s1 += a1.x*b1.x + a1.y*b1.y + a1.z*b1.z + a1.w*b1.w;
        s2 += a2.x*b2.x + a2.y*b2.y + a2.z*b2.z + a2.w*b2.w;
        s3 += a3.x*b3.x + a3.y*b3.y + a3.z*b3.z + a3.w*b3.w;
    }
    return (s0+s1)+(s2+s3);
}

// ============ K1: stream copy + xsum (+ inline precompute) ============
__global__ __launch_bounds__(128)
void k1_stream(const float* __restrict__ x, float* __restrict__ x_copy,
               const float* __restrict__ W_enc, const float* __restrict__ b_enc,
               const float* __restrict__ pos) {
    __shared__ __align__(16) float redq[4][NL];
    __shared__ __align__(16) float xsumS[NL];

    const int tid  = threadIdx.x;
    const int pid  = blockIdx.x;
    const int lane = tid & 31;
    const int wrp  = tid >> 5;
    const float4* __restrict__ pos4 = (const float4*)pos;
    const float4* __restrict__ W4   = (const float4*)W_enc;

    // inline precompute (first NPRE blocks; wave-1 co-resident)
    if (pid < NPRE) {
        if (pid == 0) {
            float a0=0.f, a1=0.f, a2=0.f, a3=0.f;
            #pragma unroll 2
            for (int n = 0; n < 252; n += 4) {
                a0 += __ldg(pos + (n+0)*NH + tid);
                a1 += __ldg(pos + (n+1)*NH + tid);
                a2 += __ldg(pos + (n+2)*NH + tid);
                a3 += __ldg(pos + (n+3)*NH + tid);
            }
            a0 += __ldg(pos + 252*NH + tid);
            a1 += __ldg(pos + 253*NH + tid);
            g_constvec[tid] = (float)NN * b_enc[tid] + ((a0+a1)+(a2+a3));
            __threadfence();
            __syncthreads();
            if (tid == 0) atomicAdd(&g_flag1, 1);
        } else if (pid <= 34) {
            int j = (pid-1)*128 + tid;
            if (j < NN*NL) {                         // M
                g_M[j] = dot128(pos4 + (j>>4)*32, W4 + (j&15)*32);
            } else if (j < NN*NL + NL*NL) {          // G
                int k = j - NN*NL;
                g_G[k] = dot128(W4 + (k>>4)*32, W4 + (k&15)*32);
            }
        } else {
            if (tid == 0) { while (ld_acq(&g_flag1) == 0) {} }
            __syncthreads();
            const float4* cv4 = (const float4*)g_constvec;
            int j = (pid-35)*128 + tid;
            if (j < NN) {                            // D2
                g_D2[j] = dot128(pos4 + j*32, cv4);
            } else if (j < NN + NL) {                // u
                g_u[j-NN] = dot128(W4 + (j-NN)*32, cv4);
            } else if (j < NN + 2*NL) {              // wb
                g_wb[j-NN-NL] = dot128(W4 + (j-NN-NL)*32, (const float4*)b_enc);
            } else if (j == NN + 2*NL) {             // s0
                g_s0 = dot128((const float4*)b_enc, cv4);
            }
        }
        // precompute results consumed only by K2 (after kernel boundary)
    }

    // streaming: copy x -> x_copy, accumulate xsum partials
    const float4* __restrict__ xp4 = (const float4*)(x + (size_t)pid * XPP);
    float4* __restrict__ xc4 = (float4*)(x_copy + (size_t)pid * XPP);

    float ls0=0.f, ls1=0.f, ls2=0.f, ls3=0.f;
    #pragma unroll
    for (int it = 0; it < 8; it++) {
        int i = tid + it*128;
        if (i < XPP/4) {
            float4 v = xp4[i];
            xc4[i] = v;                    // default store: keep in L2
            ls0 += v.x; ls1 += v.y; ls2 += v.z; ls3 += v.w;
        }
    }
    #pragma unroll
    for (int m = 4; m <= 16; m <<= 1) {
        ls0 += __shfl_xor_sync(0xffffffffu, ls0, m);
        ls1 += __shfl_xor_sync(0xffffffffu, ls1, m);
        ls2 += __shfl_xor_sync(0xffffffffu, ls2, m);
        ls3 += __shfl_xor_sync(0xffffffffu, ls3, m);
    }
    if (lane < 4) {
        float* rr = &redq[wrp][lane*4];
        rr[0] = ls0; rr[1] = ls1; rr[2] = ls2; rr[3] = ls3;
    }
    __syncthreads();
    if (tid < NL) {
        xsumS[tid] = (redq[0][tid] + redq[1][tid]) + (redq[2][tid] + redq[3][tid]);
        g_xsum[pid*NL + tid] = xsumS[tid];
    }
}

// ============ K2: score + pool + FF (x is L2-hot) ============
__global__ __launch_bounds__(128, 6)
void k2_main(const float* __restrict__ x,
             const float* __restrict__ W1, const float* __restrict__ b1,
             const float* __restrict__ W2, const float* __restrict__ b2,
             float* __restrict__ out_t) {
    __shared__ float sc[256];                     // scores (254 + 2 zero pad)
    __shared__ __align__(16) float redq[4][NL];
    __shared__ __align__(16) float xsumS[NL];
    __shared__ __align__(16) float vS[NL];
    __shared__ __align__(16) float pooledS[NL];
    __shared__ float hdnS[NH];
    __shared__ float warpsum[4];
    __shared__ __align__(16) float red7[4][NP];
    __shared__ float sS, invS;

    const int tid  = threadIdx.x;
    const int pid  = blockIdx.x;
    const int lane = tid & 31;
    const int wrp  = tid >> 5;
    const int q    = tid & 3;          // l-quarter index
    const int r    = tid >> 2;         // row-within-32 index

    const float4* __restrict__ xp4 = (const float4*)(x + (size_t)pid * XPP);

    // Load x -> registers (L2-hot from K1); independent of v/s computation below.
    float4 xv[8];
    #pragma unroll
    for (int it = 0; it < 8; it++) {
        int i = tid + it*128;
        xv[it] = (i < XPP/4) ? xp4[i] : make_float4(0.f, 0.f, 0.f, 0.f);
    }

    if (tid < NL) xsumS[tid] = g_xsum[pid*NL + tid];
    if (tid == 127) { sc[254] = 0.f; sc[255] = 0.f; }
    __syncthreads();

    // v = G^T xsum + u ; s = xsum.wb + s0
    if (tid < NL) {
        float a = g_u[tid];
        #pragma unroll
        for (int lp = 0; lp < NL; lp++) a += xsumS[lp] * g_G[lp*NL + tid];
        vS[tid] = a;
    }
    if (tid == 16) {
        float a = g_s0;
        #pragma unroll
        for (int l = 0; l < NL; l++) a += xsumS[l] * g_wb[l];
        sS = a;
    }
    __syncthreads();

    // score[n] = s + D2[n] + x[n].v + xsum.M[n]
    float4 vq  = ((const float4*)vS)[q];
    float4 xsq = ((const float4*)xsumS)[q];
    float myabs = 0.f;
    float sloc = sS;
    #pragma unroll
    for (int it = 0; it < 8; it++) {
        int n = it*32 + r;
        float part = 0.f;
        if (n < NN) {
            float4 m = *(const float4*)(g_M + n*NL + q*4);
            part = xv[it].x*vq.x + xv[it].y*vq.y + xv[it].z*vq.z + xv[it].w*vq.w
                 + xsq.x*m.x + xsq.y*m.y + xsq.z*m.z + xsq.w*m.w;
        }
        part += __shfl_xor_sync(0xffffffffu, part, 1);
        part += __shfl_xor_sync(0xffffffffu, part, 2);
        if (q == 0 && n < NN) {
            float a = part + sloc + g_D2[n];
            sc[n] = a;
            myabs += fabsf(a);
        }
    }
    #pragma unroll
    for (int off = 16; off; off >>= 1)
        myabs += __shfl_down_sync(0xffffffffu, myabs, off);
    if (lane == 0) warpsum[wrp] = myabs;
    __syncthreads();
    if (tid == 0)
        invS = 1.0f / ((warpsum[0] + warpsum[1]) + (warpsum[2] + warpsum[3]));
    __syncthreads();

    // pooled[l] = invS * sum_n x[n,l]*score[n]
    {
        float p0=0.f, p1=0.f, p2=0.f, p3=0.f;
        #pragma unroll
        for (int it = 0; it < 8; it++) {
            int n = it*32 + r;              // n <= 255; sc[254..255]=0
            float w = sc[n];
            p0 += xv[it].x * w;
            p1 += xv[it].y * w;
            p2 += xv[it].z * w;
            p3 += xv[it].w * w;
        }
        #pragma unroll
        for (int m = 4; m <= 16; m <<= 1) {
            p0 += __shfl_xor_sync(0xffffffffu, p0, m);
            p1 += __shfl_xor_sync(0xffffffffu, p1, m);
            p2 += __shfl_xor_sync(0xffffffffu, p2, m);
            p3 += __shfl_xor_sync(0xffffffffu, p3, m);
        }
        if (lane < 4) {
            float* rr = &redq[wrp][lane*4];
            rr[0] = p0; rr[1] = p1; rr[2] = p2; rr[3] = p3;
        }
    }
    __syncthreads();
    if (tid < NL)
        pooledS[tid] = invS * ((redq[0][tid] + redq[1][tid]) + (redq[2][tid] + redq[3][tid]));
    __syncthreads();

    // hidden = leaky_relu(pooled @ W1 + b1, 0.2)   (tid = h)
    {
        float a = b1[tid];
        #pragma unroll
        for (int l = 0; l < NL; l++) a += pooledS[l] * __ldg(W1 + l*NH + tid);
        hdnS[tid] = a > 0.f ? a : 0.2f * a;
    }
    __syncthreads();

    // out[p] = hidden @ W2 + b2 ; warp w covers h in [32w,32w+32)
    if (lane < 24) {
        const float4* __restrict__ W24 = (const float4*)W2;
        float4 acc = make_float4(0.f, 0.f, 0.f, 0.f);
        #pragma unroll 8
        for (int hh = 0; hh < 32; hh++) {
            int h = wrp*32 + hh;
            float hv = hdnS[h];
            float4 w4 = __ldg(&W24[h*24 + lane]);
            acc.x += hv*w4.x; acc.y += hv*w4.y; acc.z += hv*w4.z; acc.w += hv*w4.w;
        }
        ((float4*)red7[wrp])[lane] = acc;
    }
    __syncthreads();
    if (tid < NP) {
        float a = b2[tid] + (red7[0][tid] + red7[1][tid]) + (red7[2][tid] + red7[3][tid]);
        int b = pid >> 6, d = pid & 63;
        out_t[b*(NP*ND) + tid*ND + d] = a;
    }
}

extern "C" void kernel_launch(void* const* d_in, const int* in_sizes, int n_in,
                              void* d_out, int out_size) {
    const float* x     = (const float*)d_in[0];
    const float* W_enc = (const float*)d_in[1];
    const float* b_enc = (const float*)d_in[2];
    const float* W1    = (const float*)d_in[3];
    const float* b1    = (const float*)d_in[4];
    const float* W2    = (const float*)d_in[5];
    const float* b2    = (const float*)d_in[6];
    const float* pos   = (const float*)d_in[7];

    float* out   = (float*)d_out;          // (B,P,D) first
    float* xcopy = out + OUT_T_ELEMS;      // then p = x passthrough

    k1_stream<<<PAIRS, 128>>>(x, xcopy, W_enc, b_enc, pos);
    k2_main<<<PAIRS, 128>>>(x, W1, b1, W2, b2, out);
}

// round 8
// speedup vs baseline: 1.0243x; 1.0243x over previous
#include <cuda_runtime.h>
#include <cuda_bf16.h>

// Shapes (fixed): B=32, D=64, N=254, L=16, H=128, P=96
#define NB 32
#define ND 64
#define NN 254
#define NL 16
#define NH 128
#define NP 96
#define PAIRS (NB*ND)          // 2048
#define XPP (NN*NL)            // 4064 floats per (b,d) pair
#define OUT_T_ELEMS (NB*NP*ND) // 196608
#define NPRE 38                // producer blocks

// ---- shared precomputed tensors (tiny) ----
__device__ __align__(16) float g_constvec[NH];
__device__ __align__(16) float g_M[NN*NL];   // M[n,l] = pos[n,:] . W_enc[l,:]
__device__ __align__(16) float g_D2[NN];     // pos[n,:] . constvec
__device__ __align__(16) float g_G[NL*NL];   // G[l',l] = W_enc[l',:] . W_enc[l,:]
__device__ __align__(16) float g_u[NL];      // W_enc[l,:] . constvec
__device__ __align__(16) float g_wb[NL];     // W_enc[l,:] . b_enc
__device__ float g_s0;                        // b_enc . constvec
__device__ int g_flag1;                       // constvec ready (monotone across replays)
__device__ int g_done;                        // precompute producers done (monotone)

__device__ __forceinline__ int ld_acq(const int* p) {
    int v;
    asm volatile("ld.acquire.gpu.global.b32 %0, [%1];" : "=r"(v) : "l"(p));
    return v;
}

// vectorized length-128 dot with 4 accumulators
__device__ __forceinline__ float dot128(const float4* __restrict__ a,
                                        const float4* __restrict__ b) {
    float s0=0.f, s1=0.f, s2=0.f, s3=0.f;
    #pragma unroll
    for (int i = 0; i < 32; i += 4) {
        float4 a0=a[i],   b0=b[i];
        float4 a1=a[i+1], b1=b[i+1];
        float4 a2=a[i+2], b2=b[i+2];
        float4 a3=a[i+3], b3=b[i+3];
        s0 += a0.x*b0.x + a0.y*b0.y + a0.z*b0.z + a0.w*b0.w;
        s1 += a1.x*b1.x + a1.y*b1.y + a1.z*b1.z + a1.w*b1.w;
        s2 += a2.x*b2.x + a2.y*b2.y + a2.z*b2.z + a2.w*b2.w;
        s3 += a3.x*b3.x + a3.y*b3.y + a3.z*b3.z + a3.w*b3.w;
    }
    return (s0+s1)+(s2+s3);
}

__global__ __launch_bounds__(128)
void k_all(const float* __restrict__ x, float* __restrict__ x_copy,
           const float* __restrict__ W_enc, const float* __restrict__ b_enc,
           const float* __restrict__ pos,
           const float* __restrict__ W1, const float* __restrict__ b1,
           const float* __restrict__ W2, const float* __restrict__ b2,
           float* __restrict__ out_t) {
    __shared__ __align__(16) float redq[4][NL];   // per-warp quarter reductions
    __shared__ __align__(16) float xsumS[NL];
    __shared__ __align__(16) float vS[NL];
    __shared__ __align__(16) float pooledS[NL];   // UNNORMALIZED pooled
    __shared__ float warpsum[4];
    __shared__ __align__(16) float red7[4][NP];   // FF cross-warp partials
    __shared__ float sS, invS;

    const int tid  = threadIdx.x;
    const int pid  = blockIdx.x;
    const int lane = tid & 31;
    const int wrp  = tid >> 5;
    const int q    = tid & 3;          // l-quarter index
    const int r    = tid >> 2;         // row-within-32 index
    const float4* __restrict__ pos4 = (const float4*)pos;
    const float4* __restrict__ W4   = (const float4*)W_enc;

    // ---------- inline precompute (first NPRE blocks, wave-1 co-resident) ----------
    if (pid < NPRE) {
        if (pid == 0) {
            float a0=0.f, a1=0.f, a2=0.f, a3=0.f;
            #pragma unroll 2
            for (int n = 0; n < 252; n += 4) {
                a0 += __ldg(pos + (n+0)*NH + tid);
                a1 += __ldg(pos + (n+1)*NH + tid);
                a2 += __ldg(pos + (n+2)*NH + tid);
                a3 += __ldg(pos + (n+3)*NH + tid);
            }
            a0 += __ldg(pos + 252*NH + tid);
            a1 += __ldg(pos + 253*NH + tid);
            g_constvec[tid] = (float)NN * b_enc[tid] + ((a0+a1)+(a2+a3));
            __threadfence();
            __syncthreads();
            if (tid == 0) atomicAdd(&g_flag1, 1);
        } else if (pid <= 34) {
            int j = (pid-1)*128 + tid;
            if (j < NN*NL) {                         // M
                g_M[j] = dot128(pos4 + (j>>4)*32, W4 + (j&15)*32);
            } else if (j < NN*NL + NL*NL) {          // G
                int k = j - NN*NL;
                g_G[k] = dot128(W4 + (k>>4)*32, W4 + (k&15)*32);
            }
        } else {
            if (tid == 0) { while (ld_acq(&g_flag1) == 0) {} }
            __syncthreads();
            const float4* cv4 = (const float4*)g_constvec;
            int j = (pid-35)*128 + tid;
            if (j < NN) {                            // D2
                g_D2[j] = dot128(pos4 + j*32, cv4);
            } else if (j < NN + NL) {                // u
                g_u[j-NN] = dot128(W4 + (j-NN)*32, cv4);
            } else if (j < NN + 2*NL) {              // wb
                g_wb[j-NN-NL] = dot128(W4 + (j-NN-NL)*32, (const float4*)b_enc);
            } else if (j == NN + 2*NL) {             // s0
                g_s0 = dot128((const float4*)b_enc, cv4);
            }
        }
        __threadfence();
        __syncthreads();
        if (tid == 0) atomicAdd(&g_done, 1);
    }

    // ---------- main per-pair work (all 2048 blocks) ----------
    const float4* __restrict__ xp4 = (const float4*)(x + (size_t)pid * XPP);
    float4* __restrict__ xc4 = (float4*)(x_copy + (size_t)pid * XPP);

    // Phase 1: stream x -> registers + fused passthrough copy + xsum partials.
    // Thread (4r+q) holds l-quarter q of rows n = it*32 + r, it = 0..7.
    float4 xv[8];
    float ls0=0.f, ls1=0.f, ls2=0.f, ls3=0.f;
    #pragma unroll
    for (int it = 0; it < 8; it++) {
        int i = tid + it*128;
        if (i < XPP/4) {
            float4 v = __ldcs(xp4 + i);
            __stcs(xc4 + i, v);
            xv[it] = v;
            ls0 += v.x; ls1 += v.y; ls2 += v.z; ls3 += v.w;
        } else {
            xv[it] = make_float4(0.f, 0.f, 0.f, 0.f);
        }
    }
    #pragma unroll
    for (int m = 4; m <= 16; m <<= 1) {
        ls0 += __shfl_xor_sync(0xffffffffu, ls0, m);
        ls1 += __shfl_xor_sync(0xffffffffu, ls1, m);
        ls2 += __shfl_xor_sync(0xffffffffu, ls2, m);
        ls3 += __shfl_xor_sync(0xffffffffu, ls3, m);
    }
    if (lane < 4) {
        float* rr = &redq[wrp][lane*4];
        rr[0] = ls0; rr[1] = ls1; rr[2] = ls2; rr[3] = ls3;
    }
    // precompute-done spin BEFORE the barrier that releases vS/sS computation
    if (tid == 64) { while (ld_acq(&g_done) < NPRE) {} }
    __syncthreads();                                    // SYNC 1

    // xsum finalize + v = G^T xsum + u ; sS = xsum.wb + s0
    if (tid < NL) {
        float s = (redq[0][tid] + redq[1][tid]) + (redq[2][tid] + redq[3][tid]);
        xsumS[tid] = s;
    }
    __syncthreads();                                    // SYNC 2
    if (tid < NL) {
        float a = g_u[tid];
        #pragma unroll
        for (int lp = 0; lp < NL; lp++) a += xsumS[lp] * g_G[lp*NL + tid];
        vS[tid] = a;
    }
    if (tid == 16) {
        float a = g_s0;
        #pragma unroll
        for (int l = 0; l < NL; l++) a += xsumS[l] * g_wb[l];
        sS = a;
    }
    __syncthreads();                                    // SYNC 3

    // Fused score + pool: score[n] broadcast to all 4 lanes of its q-group,
    // pooled quarters accumulated immediately (unnormalized).
    float4 vq  = ((const float4*)vS)[q];
    float4 xsq = ((const float4*)xsumS)[q];
    const float sloc = sS;
    float myabs = 0.f;
    float p0=0.f, p1=0.f, p2=0.f, p3=0.f;
    #pragma unroll
    for (int it = 0; it < 8; it++) {
        int n = it*32 + r;
        float part = 0.f;
        float d2 = 0.f;
        if (n < NN) {
            float4 m = *(const float4*)(g_M + n*NL + q*4);
            part = xv[it].x*vq.x + xv[it].y*vq.y + xv[it].z*vq.z + xv[it].w*vq.w
                 + xsq.x*m.x + xsq.y*m.y + xsq.z*m.z + xsq.w*m.w;
            d2 = g_D2[n];
        }
        part += __shfl_xor_sync(0xffffffffu, part, 1);
        part += __shfl_xor_sync(0xffffffffu, part, 2);   // all 4 lanes have dot total
        float a = part + sloc + d2;                      // score[n] (garbage if n>=NN but xv=0)
        if (n < NN) {
            p0 += xv[it].x * a;
            p1 += xv[it].y * a;
            p2 += xv[it].z * a;
            p3 += xv[it].w * a;
            if (q == 0) myabs += fabsf(a);
        }
    }
    // reduce pooled quarters (masks 4,8,16) and abs-sum (q==0 lanes hold values)
    #pragma unroll
    for (int m = 4; m <= 16; m <<= 1) {
        p0 += __shfl_xor_sync(0xffffffffu, p0, m);
        p1 += __shfl_xor_sync(0xffffffffu, p1, m);
        p2 += __shfl_xor_sync(0xffffffffu, p2, m);
        p3 += __shfl_xor_sync(0xffffffffu, p3, m);
        myabs += __shfl_xor_sync(0xffffffffu, myabs, m);
    }
    if (lane < 4) {
        float* rr = &redq[wrp][lane*4];
        rr[0] = p0; rr[1] = p1; rr[2] = p2; rr[3] = p3;
    }
    if (lane == 0) warpsum[wrp] = myabs;
    __syncthreads();                                    // SYNC 4
    if (tid < NL)
        pooledS[tid] = (redq[0][tid] + redq[1][tid]) + (redq[2][tid] + redq[3][tid]);
    if (tid == 16)
        invS = 1.0f / ((warpsum[0] + warpsum[1]) + (warpsum[2] + warpsum[3]));
    __syncthreads();                                    // SYNC 5

    // FF: warp w owns h = 32w + lane. hidden kept in-register, shfl-broadcast.
    float hdn;
    {
        int h = wrp*32 + lane;
        float a = 0.f;
        #pragma unroll
        for (int l = 0; l < NL; l++) a += pooledS[l] * __ldg(W1 + l*NH + h);
        a = b1[h] + a * invS;
        hdn = a > 0.f ? a : 0.2f * a;
    }
    // out partials: warp w covers its own h-range via shuffle broadcast
    {
        const float4* __restrict__ W24 = (const float4*)W2;  // [h][24] float4s
        float4 acc = make_float4(0.f, 0.f, 0.f, 0.f);
        #pragma unroll 8
        for (int hh = 0; hh < 32; hh++) {
            float hv = __shfl_sync(0xffffffffu, hdn, hh);
            if (lane < 24) {
                int h = wrp*32 + hh;
                float4 w4 = __ldg(&W24[h*24 + lane]);
                acc.x += hv*w4.x; acc.y += hv*w4.y; acc.z += hv*w4.z; acc.w += hv*w4.w;
            }
        }
        if (lane < 24) ((float4*)red7[wrp])[lane] = acc;
    }
    __syncthreads();                                    // SYNC 6
    if (tid < NP) {
        float a = b2[tid] + (red7[0][tid] + red7[1][tid]) + (red7[2][tid] + red7[3][tid]);
        int b = pid >> 6, d = pid & 63;
        out_t[b*(NP*ND) + tid*ND + d] = a;
    }
}

extern "C" void kernel_launch(void* const* d_in, const int* in_sizes, int n_in,
                              void* d_out, int out_size) {
    const float* x     = (const float*)d_in[0];
    const float* W_enc = (const float*)d_in[1];
    const float* b_enc = (const float*)d_in[2];
    const float* W1    = (const float*)d_in[3];
    const float* b1    = (const float*)d_in[4];
    const float* W2    = (const float*)d_in[5];
    const float* b2    = (const float*)d_in[6];
    const float* pos   = (const float*)d_in[7];

    float* out   = (float*)d_out;          // (B,P,D) first
    float* xcopy = out + OUT_T_ELEMS;      // then p = x passthrough

    k_all<<<PAIRS, 128>>>(x, xcopy, W_enc, b_enc, pos, W1, b1, W2, b2, out);
}